// round 5
// baseline (speedup 1.0000x reference)
#include <cuda_runtime.h>

// MonarchAttention on GB300 — fp32 batched 64x64x64 smem GEMMs (scalar FFMA),
// XOR-swizzled smem operands, buffer reuse -> 48KB/CTA -> 4 CTAs/SM.
// B=4,H=16 -> BH=64; N=4096, D=64, b=m=64, STEPS=3.
//
// Layouts (fp32):
//   Q/K/V   : [bh][blk][intra][d]
//   g_qbar  : [bh][j][s][d]
//   g_kbar  : [bh][s][j][d]
//   g_vbar  : [bh][s][j][d]
//   g_ent   : [bh][s][j]     g_qmean : [bh][s][d]
//
// Smem operand layout (64x64, k-major, swizzled):
//   (k, idx) -> k*64 + ((((idx>>2) ^ (k & 15)) << 2) | (idx & 3))
//   GEMM loads: float4 at k*64 + ((grp ^ (k&15))<<2), grp = idx>>2.

#define SCALE 0.125f
#define SWZ(k, i) (((k) << 6) + (((((i) >> 2) ^ ((k) & 15)) << 2) | ((i) & 3)))

__device__ float g_qmean[262144];
__device__ float g_ent  [262144];
__device__ float g_qbar [16777216];
__device__ float g_kbar [16777216];
__device__ float g_vbar [16777216];

// ---------------------------------------------------------------------------
__device__ __forceinline__ float redmax16(float v) {
#pragma unroll
    for (int m = 8; m; m >>= 1) v = fmaxf(v, __shfl_xor_sync(0xffffffffu, v, m));
    return v;
}
__device__ __forceinline__ float redsum16(float v) {
#pragma unroll
    for (int m = 8; m; m >>= 1) v += __shfl_xor_sync(0xffffffffu, v, m);
    return v;
}

// C[r][c] += sum_k A[k][ty4+r] * B[k][tx4+c], swizzled operands.
__device__ __forceinline__ void mmswz(const float* __restrict__ sA,
                                      const float* __restrict__ sB,
                                      int ty, int tx, float acc[4][4]) {
#pragma unroll 8
    for (int k = 0; k < 64; ++k) {
        int g = k & 15;
        float4 av = *reinterpret_cast<const float4*>(sA + (k << 6) + ((ty ^ g) << 2));
        float4 bv = *reinterpret_cast<const float4*>(sB + (k << 6) + ((tx ^ g) << 2));
        const float a[4] = {av.x, av.y, av.z, av.w};
        const float b[4] = {bv.x, bv.y, bv.z, bv.w};
#pragma unroll
        for (int r = 0; r < 4; ++r)
#pragma unroll
            for (int c = 0; c < 4; ++c)
                acc[r][c] = fmaf(a[r], b[c], acc[r][c]);
    }
}

// ---------------------------------------------------------------------------
// qmean[bh][s][d] = mean_i Q[bh][i][s][d]   (step-0 qbar, j-independent)
// ---------------------------------------------------------------------------
__global__ void qmean_kernel(const float* __restrict__ Q) {
    int bid = blockIdx.x;
    int bh = bid >> 4;
    int s = ((bid & 15) << 2) + (threadIdx.x >> 6);
    int d = threadIdx.x & 63;
    const float* base = Q + bh * 262144 + s * 64 + d;
    float acc = 0.f;
#pragma unroll 16
    for (int i = 0; i < 64; ++i) acc += base[i * 4096];
    g_qmean[(bh << 6 | s) * 64 + d] = acc * (1.0f / 64.0f);
}

// ---------------------------------------------------------------------------
// B: per (bh,j): S=scale*qbar_j K^T; R=softmax_t; ent; kbar=R K; (vbar=R V)
// grid 4096, 256 thr, smem 49152B (3 x 16KB, reused)
// ---------------------------------------------------------------------------
__global__ void __launch_bounds__(256)
bstep_kernel(const float* __restrict__ Kg, const float* __restrict__ Vg,
             int use_qmean, int do_vbar) {
    int bid = blockIdx.x, bh = bid >> 6, j = bid & 63;
    extern __shared__ float sm[];
    float* buf0 = sm;           // qbarT (k=d,idx=s)  -> later RT (k=t,idx=s)
    float* buf1 = sm + 4096;    // KT    (k=d,idx=t)  -> later V  (k=t,idx=d)
    float* buf2 = sm + 8192;    // K     (k=t,idx=d)
    int tid = threadIdx.x;

    const float* Kb = Kg + bh * 262144 + j * 4096;
    const float* qb = use_qmean ? (g_qmean + (bh << 12))
                                : (g_qbar + bh * 262144 + j * 4096);
#pragma unroll
    for (int r = 0; r < 16; ++r) {
        int lin = (r << 8) + tid;
        int t = lin >> 6, d = lin & 63;   // row index (t or s), col d
        float v = Kb[lin];
        buf2[SWZ(t, d)] = v;
        buf1[SWZ(d, t)] = v;
        buf0[SWZ(d, t)] = qb[lin];        // qb row = s, same indexing
    }
    __syncthreads();

    int tx = tid & 15, ty = tid >> 4;
    int tx4 = tx << 2, ty4 = ty << 2;

    float S[4][4] = {};
    mmswz(buf0, buf1, ty, tx, S);         // S[s][t]

    float R[4][4];
#pragma unroll
    for (int rr = 0; rr < 4; ++rr) {
        float mx = -1e30f;
#pragma unroll
        for (int cc = 0; cc < 4; ++cc) { S[rr][cc] *= SCALE; mx = fmaxf(mx, S[rr][cc]); }
        mx = redmax16(mx);
        float sum = 0.f;
#pragma unroll
        for (int cc = 0; cc < 4; ++cc) { R[rr][cc] = __expf(S[rr][cc] - mx); sum += R[rr][cc]; }
        sum = redsum16(sum);
        float inv = 1.0f / sum, lsum = __logf(sum), e = 0.f;
#pragma unroll
        for (int cc = 0; cc < 4; ++cc) {
            float rv = R[rr][cc] * inv;
            e += rv * (S[rr][cc] - mx - lsum);
            R[rr][cc] = rv;
        }
        e = redsum16(e);
        if (tx == 0) g_ent[((bh << 6) + ty4 + rr) * 64 + j] = -e;
    }
    __syncthreads();   // everyone done reading buf0/buf1

    // scatter R^T into buf0 as (k=t, idx=s); stage V into buf1 if needed
#pragma unroll
    for (int rr = 0; rr < 4; ++rr)
#pragma unroll
        for (int cc = 0; cc < 4; ++cc)
            buf0[SWZ(tx4 + cc, ty4 + rr)] = R[rr][cc];
    if (do_vbar) {
        const float* Vb = Vg + bh * 262144 + j * 4096;
#pragma unroll
        for (int r = 0; r < 16; ++r) {
            int lin = (r << 8) + tid;
            int t = lin >> 6, d = lin & 63;
            buf1[SWZ(t, d)] = Vb[lin];
        }
    }
    __syncthreads();

    // kbar[s][d] = sum_t R[s][t] K[t][d]
    float acc[4][4] = {};
    mmswz(buf0, buf2, ty, tx, acc);
#pragma unroll
    for (int rr = 0; rr < 4; ++rr) {
        int s = ty4 + rr;
        *reinterpret_cast<float4*>(g_kbar + ((bh << 6 | s) << 12) + (j << 6) + tx4) =
            make_float4(acc[rr][0], acc[rr][1], acc[rr][2], acc[rr][3]);
    }
    if (do_vbar) {
        float av[4][4] = {};
        mmswz(buf0, buf1, ty, tx, av);
#pragma unroll
        for (int rr = 0; rr < 4; ++rr) {
            int s = ty4 + rr;
            *reinterpret_cast<float4*>(g_vbar + ((bh << 6 | s) << 12) + (j << 6) + tx4) =
                make_float4(av[rr][0], av[rr][1], av[rr][2], av[rr][3]);
        }
    }
}

// ---------------------------------------------------------------------------
// C (fused): per (bh,s):
//   SL = scale*Q kbar^T + ent;  L = softmax_j(SL)
//   non-final: w[j]=sum_i L[i][j];  qbar[j][d]=(sum_i L[i][j]Q[i][d])/w[j]
//   final:     out[i][d] = sum_j L[i][j] vbar[j][d]
// grid 4096, 256 thr, smem 49664B
// ---------------------------------------------------------------------------
__global__ void __launch_bounds__(256)
cstep_kernel(const float* __restrict__ Qg, float* __restrict__ out, int is_final) {
    int bid = blockIdx.x, bh = bid >> 6, s = bid & 63;
    extern __shared__ float sm[];
    float* buf0 = sm;           // QT    (k=d, idx=i)
    float* buf1 = sm + 4096;    // kbarT (k=d, idx=j) -> later L (nf: k=i,idx=j | f: k=j,idx=i)
    float* buf2 = sm + 8192;    // nf: Q (k=i, idx=d) | f: vbar (k=j, idx=d)
    float* sEnt = sm + 12288;   // [64]
    float* sW   = sm + 12352;   // [64]
    int tid = threadIdx.x;

    const float* Qb = Qg + bh * 262144 + s * 64;
    const float* kb = g_kbar + ((bh << 6 | s) << 12);
#pragma unroll
    for (int r = 0; r < 16; ++r) {
        int lin = (r << 8) + tid;
        int row = lin >> 6, d = lin & 63;   // row = i (Q) or j (kbar)
        float qv = Qb[row * 4096 + d];
        buf0[SWZ(d, row)] = qv;
        if (!is_final) buf2[SWZ(row, d)] = qv;
        buf1[SWZ(d, row)] = kb[lin];
    }
    if (is_final) {
        const float* vb = g_vbar + ((bh << 6 | s) << 12);
#pragma unroll
        for (int r = 0; r < 16; ++r) {
            int lin = (r << 8) + tid;
            int jj = lin >> 6, d = lin & 63;
            buf2[SWZ(jj, d)] = vb[lin];
        }
    }
    if (tid < 64) sEnt[tid] = g_ent[((bh << 6) + s) * 64 + tid];
    __syncthreads();

    int tx = tid & 15, ty = tid >> 4;
    int tx4 = tx << 2, ty4 = ty << 2;

    float S[4][4] = {};
    mmswz(buf0, buf1, ty, tx, S);          // S[i][j]

    float ev[4];
#pragma unroll
    for (int cc = 0; cc < 4; ++cc) ev[cc] = sEnt[tx4 + cc];

    float L[4][4];
#pragma unroll
    for (int rr = 0; rr < 4; ++rr) {
        float mx = -1e30f;
#pragma unroll
        for (int cc = 0; cc < 4; ++cc) {
            S[rr][cc] = S[rr][cc] * SCALE + ev[cc];
            mx = fmaxf(mx, S[rr][cc]);
        }
        mx = redmax16(mx);
        float sum = 0.f;
#pragma unroll
        for (int cc = 0; cc < 4; ++cc) { L[rr][cc] = __expf(S[rr][cc] - mx); sum += L[rr][cc]; }
        sum = redsum16(sum);
        float inv = 1.0f / sum;
#pragma unroll
        for (int cc = 0; cc < 4; ++cc) L[rr][cc] *= inv;
    }
    __syncthreads();   // done reading buf1

    if (!is_final) {
        // scatter L as (k=i, idx=j) into buf1
#pragma unroll
        for (int rr = 0; rr < 4; ++rr)
#pragma unroll
            for (int cc = 0; cc < 4; ++cc)
                buf1[SWZ(ty4 + rr, tx4 + cc)] = L[rr][cc];
        __syncthreads();
        if (tid < 64) {
            float a = 0.f;
#pragma unroll 8
            for (int i = 0; i < 64; ++i) a += buf1[SWZ(i, tid)];
            sW[tid] = 1.0f / a;
        }
        __syncthreads();
        // qbar[j][d] = (sum_i L[i][j] Q[i][d]) / w[j]
        float acc[4][4] = {};
        mmswz(buf1, buf2, ty, tx, acc);
        float* ob = g_qbar + bh * 262144 + s * 64 + tx4;
#pragma unroll
        for (int rr = 0; rr < 4; ++rr) {
            int j = ty4 + rr;
            float w = sW[j];
            *reinterpret_cast<float4*>(ob + j * 4096) =
                make_float4(acc[rr][0] * w, acc[rr][1] * w,
                            acc[rr][2] * w, acc[rr][3] * w);
        }
    } else {
        // scatter L^T as (k=j, idx=i) into buf1
#pragma unroll
        for (int rr = 0; rr < 4; ++rr)
#pragma unroll
            for (int cc = 0; cc < 4; ++cc)
                buf1[SWZ(tx4 + cc, ty4 + rr)] = L[rr][cc];
        __syncthreads();
        // out[i][d] = sum_j L[i][j] vbar[j][d]
        float acc[4][4] = {};
        mmswz(buf1, buf2, ty, tx, acc);
        float* ob = out + bh * 262144 + s * 64 + tx4;
#pragma unroll
        for (int rr = 0; rr < 4; ++rr)
            *reinterpret_cast<float4*>(ob + (ty4 + rr) * 4096) =
                make_float4(acc[rr][0], acc[rr][1], acc[rr][2], acc[rr][3]);
    }
}

// ---------------------------------------------------------------------------
extern "C" void kernel_launch(void* const* d_in, const int* in_sizes, int n_in,
                              void* d_out, int out_size) {
    const float* Q = (const float*)d_in[0];
    const float* K = (const float*)d_in[1];
    const float* V = (const float*)d_in[2];
    float* out = (float*)d_out;

    const int SM_B = 12288 * 4;   // 49152
    const int SM_C = 12416 * 4;   // 49664
    cudaFuncSetAttribute(bstep_kernel, cudaFuncAttributeMaxDynamicSharedMemorySize, SM_B);
    cudaFuncSetAttribute(cstep_kernel, cudaFuncAttributeMaxDynamicSharedMemorySize, SM_C);

    // step 0 (uniform L -> qbar == per-s mean of Q)
    qmean_kernel<<<1024, 256>>>(Q);
    bstep_kernel<<<4096, 256, SM_B>>>(K, V, 1, 0);
    cstep_kernel<<<4096, 256, SM_C>>>(Q, out, 0);   // L-update + qbar for step 1
    // step 1
    bstep_kernel<<<4096, 256, SM_B>>>(K, V, 0, 0);
    cstep_kernel<<<4096, 256, SM_C>>>(Q, out, 0);   // L-update + qbar for step 2
    // step 2
    bstep_kernel<<<4096, 256, SM_B>>>(K, V, 0, 1);  // also vbar
    cstep_kernel<<<4096, 256, SM_C>>>(Q, out, 1);   // final: out = L vbar
}

// round 6
// speedup vs baseline: 1.1361x; 1.1361x over previous
#include <cuda_runtime.h>

// MonarchAttention on GB300 — fp32 batched 64x64x64 smem GEMMs, 8x4 register
// tiles (128 thr/CTA) to cut LDS traffic per FMA from 2B to 1.5B.
// B=4,H=16 -> BH=64; N=4096, D=64, b=m=64, STEPS=3.
//
// Layouts (fp32):
//   Q/K/V   : [bh][blk][intra][d]
//   g_qbar  : [bh][j][s][d]
//   g_kbar  : [bh][s][j][d]
//   g_vbar  : [bh][s][j][d]
//   g_ent   : [bh][s][j]     g_qmean : [bh][s][d]

#define SCALE 0.125f
// swizzled layout for scatter-built operands (k-major, 64 floats/row):
#define SWZ64(k, i) (((k) << 6) + (((((i) >> 2) ^ ((k) & 15)) << 2) | ((i) & 3)))

__device__ float g_qmean[262144];
__device__ float g_ent  [262144];
__device__ float g_qbar [16777216];
__device__ float g_kbar [16777216];
__device__ float g_vbar [16777216];

// ---------------------------------------------------------------------------
__device__ __forceinline__ float redmax16(float v) {
#pragma unroll
    for (int m = 8; m; m >>= 1) v = fmaxf(v, __shfl_xor_sync(0xffffffffu, v, m));
    return v;
}
__device__ __forceinline__ float redsum16(float v) {
#pragma unroll
    for (int m = 8; m; m >>= 1) v += __shfl_xor_sync(0xffffffffu, v, m);
    return v;
}

// acc[r][c] += sum_k A[k][ty8+r] * B[k][tx4+c]; A stride SA, B stride SB.
template <int SA, int SB>
__device__ __forceinline__ void mm84(const float* __restrict__ sA,
                                     const float* __restrict__ sB,
                                     int ty8, int tx4, float acc[8][4]) {
#pragma unroll 8
    for (int k = 0; k < 64; ++k) {
        float4 a0 = *reinterpret_cast<const float4*>(sA + k * SA + ty8);
        float4 a1 = *reinterpret_cast<const float4*>(sA + k * SA + ty8 + 4);
        float4 bv = *reinterpret_cast<const float4*>(sB + k * SB + tx4);
        const float a[8] = {a0.x, a0.y, a0.z, a0.w, a1.x, a1.y, a1.z, a1.w};
        const float b[4] = {bv.x, bv.y, bv.z, bv.w};
#pragma unroll
        for (int r = 0; r < 8; ++r)
#pragma unroll
            for (int c = 0; c < 4; ++c)
                acc[r][c] = fmaf(a[r], b[c], acc[r][c]);
    }
}

// A is SWZ64-swizzled (scatter-built transpose), B stride 64.
__device__ __forceinline__ void mm84swz(const float* __restrict__ sA,
                                        const float* __restrict__ sB,
                                        int ty2, int tx4, float acc[8][4]) {
#pragma unroll 8
    for (int k = 0; k < 64; ++k) {
        int g = k & 15;
        const float* base = sA + (k << 6);
        float4 a0 = *reinterpret_cast<const float4*>(base + ((ty2 ^ g) << 2));
        float4 a1 = *reinterpret_cast<const float4*>(base + (((ty2 + 1) ^ g) << 2));
        float4 bv = *reinterpret_cast<const float4*>(sB + (k << 6) + tx4);
        const float a[8] = {a0.x, a0.y, a0.z, a0.w, a1.x, a1.y, a1.z, a1.w};
        const float b[4] = {bv.x, bv.y, bv.z, bv.w};
#pragma unroll
        for (int r = 0; r < 8; ++r)
#pragma unroll
            for (int c = 0; c < 4; ++c)
                acc[r][c] = fmaf(a[r], b[c], acc[r][c]);
    }
}

// ---------------------------------------------------------------------------
// qmean[bh][s][d] = mean_i Q[bh][i][s][d]   (step-0 qbar, j-independent)
// ---------------------------------------------------------------------------
__global__ void qmean_kernel(const float* __restrict__ Q) {
    int bid = blockIdx.x;
    int bh = bid >> 4;
    int s = ((bid & 15) << 2) + (threadIdx.x >> 6);
    int d = threadIdx.x & 63;
    const float* base = Q + bh * 262144 + s * 64 + d;
    float acc = 0.f;
#pragma unroll 16
    for (int i = 0; i < 64; ++i) acc += base[i * 4096];
    g_qmean[(bh << 6 | s) * 64 + d] = acc * (1.0f / 64.0f);
}

// ---------------------------------------------------------------------------
// B: per (bh,j): S=scale*qbar_j K^T; R=softmax_t; ent; kbar=R K; (vbar=R V)
// grid 4096, 128 thr, smem 51200B
// ---------------------------------------------------------------------------
__global__ void __launch_bounds__(128)
bstep_kernel(const float* __restrict__ Kg, const float* __restrict__ Vg,
             int use_qmean, int do_vbar) {
    int bid = blockIdx.x, bh = bid >> 6, j = bid & 63;
    extern __shared__ float sm[];
    float* buf0 = sm;           // qbarT [d][s] str68  -> later RT swz (k=t,idx=s)
    float* buf1 = sm + 4352;    // KT    [d][t] str68  -> later V (k=t,idx=d) str64
    float* buf2 = sm + 8704;    // K     [t][d] str64
    int tid = threadIdx.x;

    const float* Kb = Kg + bh * 262144 + j * 4096;
    const float* qb = use_qmean ? (g_qmean + (bh << 12))
                                : (g_qbar + bh * 262144 + j * 4096);
#pragma unroll 8
    for (int r = 0; r < 32; ++r) {
        int lin = (r << 7) + tid;
        int t = lin >> 6, d = lin & 63;
        float v = Kb[lin];
        buf2[(t << 6) + d] = v;
        buf1[d * 68 + t] = v;
        buf0[d * 68 + t] = qb[lin];
    }
    __syncthreads();

    int tx = tid & 15, ty = tid >> 4;
    int tx4 = tx << 2, ty8 = ty << 3, ty2 = ty << 1;

    float S[8][4] = {};
    mm84<68, 68>(buf0, buf1, ty8, tx4, S);   // S[s][t]

    float R[8][4];
#pragma unroll
    for (int rr = 0; rr < 8; ++rr) {
        float mx = -1e30f;
#pragma unroll
        for (int cc = 0; cc < 4; ++cc) { S[rr][cc] *= SCALE; mx = fmaxf(mx, S[rr][cc]); }
        mx = redmax16(mx);
        float sum = 0.f;
#pragma unroll
        for (int cc = 0; cc < 4; ++cc) { R[rr][cc] = __expf(S[rr][cc] - mx); sum += R[rr][cc]; }
        sum = redsum16(sum);
        float inv = 1.0f / sum, lsum = __logf(sum), e = 0.f;
#pragma unroll
        for (int cc = 0; cc < 4; ++cc) {
            float rv = R[rr][cc] * inv;
            e += rv * (S[rr][cc] - mx - lsum);
            R[rr][cc] = rv;
        }
        e = redsum16(e);
        if (tx == 0) g_ent[((bh << 6) + ty8 + rr) * 64 + j] = -e;
    }
    __syncthreads();   // done reading buf0/buf1

    // scatter R^T into buf0 (swizzled, k=t idx=s); stage V into buf1 if needed
#pragma unroll
    for (int rr = 0; rr < 8; ++rr)
#pragma unroll
        for (int cc = 0; cc < 4; ++cc)
            buf0[SWZ64(tx4 + cc, ty8 + rr)] = R[rr][cc];
    if (do_vbar) {
        const float* Vb = Vg + bh * 262144 + j * 4096;
#pragma unroll 8
        for (int r = 0; r < 32; ++r) {
            int lin = (r << 7) + tid;
            int t = lin >> 6, d = lin & 63;
            buf1[(t << 6) + d] = Vb[lin];
        }
    }
    __syncthreads();

    // kbar[s][d] = sum_t R[s][t] K[t][d]
    float acc[8][4] = {};
    mm84swz(buf0, buf2, ty2, tx4, acc);
#pragma unroll
    for (int rr = 0; rr < 8; ++rr) {
        int s = ty8 + rr;
        *reinterpret_cast<float4*>(g_kbar + ((bh << 6 | s) << 12) + (j << 6) + tx4) =
            make_float4(acc[rr][0], acc[rr][1], acc[rr][2], acc[rr][3]);
    }
    if (do_vbar) {
        float av[8][4] = {};
        mm84swz(buf0, buf1, ty2, tx4, av);
#pragma unroll
        for (int rr = 0; rr < 8; ++rr) {
            int s = ty8 + rr;
            *reinterpret_cast<float4*>(g_vbar + ((bh << 6 | s) << 12) + (j << 6) + tx4) =
                make_float4(av[rr][0], av[rr][1], av[rr][2], av[rr][3]);
        }
    }
}

// ---------------------------------------------------------------------------
// C (fused): per (bh,s):
//   SL = scale*Q kbar^T + ent;  L = softmax_j(SL)
//   non-final: w[j]=sum_i L[i][j];  qbar[j][d]=(sum_i L[i][j]Q[i][d])/w[j]
//   final:     out[i][d] = sum_j L[i][j] vbar[j][d]
// grid 4096, 128 thr, smem 51712B
// ---------------------------------------------------------------------------
__global__ void __launch_bounds__(128)
cstep_kernel(const float* __restrict__ Qg, float* __restrict__ out, int is_final) {
    int bid = blockIdx.x, bh = bid >> 6, s = bid & 63;
    extern __shared__ float sm[];
    float* buf0 = sm;           // QT [d][i] str68
    float* buf1 = sm + 4352;    // kbarT [d][j] str68 -> L (nf: [i][j] str68 | f: LT swz)
    float* buf2 = sm + 8704;    // nf: Q (k=i,idx=d) str64 | f: vbar (k=j,idx=d) str64
    float* sEnt = sm + 12800;   // [64]
    float* sW   = sm + 12864;   // [64]
    int tid = threadIdx.x;

    const float* Qb = Qg + bh * 262144 + s * 64;
    const float* kb = g_kbar + ((bh << 6 | s) << 12);
#pragma unroll 8
    for (int r = 0; r < 32; ++r) {
        int lin = (r << 7) + tid;
        int row = lin >> 6, d = lin & 63;   // row = i (Q) or j (kbar)
        float qv = Qb[row * 4096 + d];
        buf0[d * 68 + row] = qv;
        if (!is_final) buf2[(row << 6) + d] = qv;
        buf1[d * 68 + row] = kb[lin];
    }
    if (is_final) {
        const float* vb = g_vbar + ((bh << 6 | s) << 12);
#pragma unroll 8
        for (int r = 0; r < 32; ++r) {
            int lin = (r << 7) + tid;
            int jj = lin >> 6, d = lin & 63;
            buf2[(jj << 6) + d] = vb[lin];
        }
    }
    if (tid < 64) sEnt[tid] = g_ent[((bh << 6) + s) * 64 + tid];
    __syncthreads();

    int tx = tid & 15, ty = tid >> 4;
    int tx4 = tx << 2, ty8 = ty << 3, ty2 = ty << 1;

    float S[8][4] = {};
    mm84<68, 68>(buf0, buf1, ty8, tx4, S);   // S[i][j]

    float ev[4];
#pragma unroll
    for (int cc = 0; cc < 4; ++cc) ev[cc] = sEnt[tx4 + cc];

    float L[8][4];
#pragma unroll
    for (int rr = 0; rr < 8; ++rr) {
        float mx = -1e30f;
#pragma unroll
        for (int cc = 0; cc < 4; ++cc) {
            S[rr][cc] = S[rr][cc] * SCALE + ev[cc];
            mx = fmaxf(mx, S[rr][cc]);
        }
        mx = redmax16(mx);
        float sum = 0.f;
#pragma unroll
        for (int cc = 0; cc < 4; ++cc) { L[rr][cc] = __expf(S[rr][cc] - mx); sum += L[rr][cc]; }
        sum = redsum16(sum);
        float inv = 1.0f / sum;
#pragma unroll
        for (int cc = 0; cc < 4; ++cc) L[rr][cc] *= inv;
    }
    __syncthreads();   // done reading buf1

    if (!is_final) {
        // scatter L as (k=i, idx=j), stride 68 (lane-consecutive j: conflict-free)
#pragma unroll
        for (int rr = 0; rr < 8; ++rr)
#pragma unroll
            for (int cc = 0; cc < 4; ++cc)
                buf1[(ty8 + rr) * 68 + tx4 + cc] = L[rr][cc];
        __syncthreads();
        if (tid < 64) {
            float a = 0.f;
#pragma unroll 8
            for (int i = 0; i < 64; ++i) a += buf1[i * 68 + tid];
            sW[tid] = 1.0f / a;
        }
        __syncthreads();
        // qbar[j][d] = (sum_i L[i][j] Q[i][d]) / w[j]
        float acc[8][4] = {};
        mm84<68, 64>(buf1, buf2, ty8, tx4, acc);
        float* ob = g_qbar + bh * 262144 + s * 64 + tx4;
#pragma unroll
        for (int rr = 0; rr < 8; ++rr) {
            int j = ty8 + rr;
            float w = sW[j];
            *reinterpret_cast<float4*>(ob + j * 4096) =
                make_float4(acc[rr][0] * w, acc[rr][1] * w,
                            acc[rr][2] * w, acc[rr][3] * w);
        }
    } else {
        // scatter L^T (swizzled, k=j idx=i)
#pragma unroll
        for (int rr = 0; rr < 8; ++rr)
#pragma unroll
            for (int cc = 0; cc < 4; ++cc)
                buf1[SWZ64(tx4 + cc, ty8 + rr)] = L[rr][cc];
        __syncthreads();
        // out[i][d] = sum_j L[i][j] vbar[j][d]
        float acc[8][4] = {};
        mm84swz(buf1, buf2, ty2, tx4, acc);
        float* ob = out + bh * 262144 + s * 64 + tx4;
#pragma unroll
        for (int rr = 0; rr < 8; ++rr)
            *reinterpret_cast<float4*>(ob + (ty8 + rr) * 4096) =
                make_float4(acc[rr][0], acc[rr][1], acc[rr][2], acc[rr][3]);
    }
}

// ---------------------------------------------------------------------------
extern "C" void kernel_launch(void* const* d_in, const int* in_sizes, int n_in,
                              void* d_out, int out_size) {
    const float* Q = (const float*)d_in[0];
    const float* K = (const float*)d_in[1];
    const float* V = (const float*)d_in[2];
    float* out = (float*)d_out;

    const int SM_B = 12800 * 4;   // 51200
    const int SM_C = 12928 * 4;   // 51712
    cudaFuncSetAttribute(bstep_kernel, cudaFuncAttributeMaxDynamicSharedMemorySize, SM_B);
    cudaFuncSetAttribute(cstep_kernel, cudaFuncAttributeMaxDynamicSharedMemorySize, SM_C);

    // step 0 (uniform L -> qbar == per-s mean of Q)
    qmean_kernel<<<1024, 256>>>(Q);
    bstep_kernel<<<4096, 128, SM_B>>>(K, V, 1, 0);
    cstep_kernel<<<4096, 128, SM_C>>>(Q, out, 0);   // L-update + qbar for step 1
    // step 1
    bstep_kernel<<<4096, 128, SM_B>>>(K, V, 0, 0);
    cstep_kernel<<<4096, 128, SM_C>>>(Q, out, 0);   // L-update + qbar for step 2
    // step 2
    bstep_kernel<<<4096, 128, SM_B>>>(K, V, 0, 1);  // also vbar
    cstep_kernel<<<4096, 128, SM_C>>>(Q, out, 1);   // final: out = L vbar
}

// round 8
// speedup vs baseline: 1.4712x; 1.2950x over previous
#include <cuda_runtime.h>
#include <cuda_bf16.h>
#include <mma.h>
#include <type_traits>

// MonarchAttention on GB300 — WMMA bf16 (HMMA) 3-term-split GEMM engine.
// Every 64x64x64 fp32 GEMM: D = Ah*Bh + Ah*Bl + Al*Bh with bf16 hi/lo split,
// fp32 accumulation (error ~2^-18, rel tol is 1e-3).
// All operands stored row-major once; transposes via wmma col_major views.
// B=4,H=16 -> BH=64; N=4096, D=64, b=m=64, STEPS=3.

using namespace nvcuda;
typedef unsigned int u32;

#define SCALE 0.125f
#define LDB 72   // bf16 tile row stride (144B: conflict-free LDSM)
#define LDC 68   // f32 C row stride

// smem layout (bytes)
#define OFF_AH 0
#define OFF_AL 9216
#define OFF_BH 18432
#define OFF_BL 27648
#define OFF_C  36864          // 64*68*4 = 17408
#define OFF_W  54272          // 128 f32 (ent + w)
#define OFF_VH 54784
#define OFF_VL 64000
#define SMEM_SMALL 54784
#define SMEM_BIG   73216

__device__ float g_qmean[262144];     // [bh][s][d]
__device__ float g_ent  [262144];     // [bh][s][j]
__device__ float g_qbar [16777216];   // [bh][j][s][d]
__device__ float g_kbar [16777216];   // [bh][s][j][d]
__device__ float g_vbar [16777216];   // [bh][s][j][d]

// ---------------------------------------------------------------------------
// staging: 64x64 f32 (row stride rs) -> hi/lo bf16 tiles, row-major stride LDB
// ---------------------------------------------------------------------------
__device__ __forceinline__ u32 pack2(float a, float b) {
    return (u32)__bfloat16_as_ushort(__float2bfloat16(a)) |
           ((u32)__bfloat16_as_ushort(__float2bfloat16(b)) << 16);
}
__device__ __forceinline__ void stageHL(__nv_bfloat16* Th, __nv_bfloat16* Tl,
                                        const float* src, int rs, int tid) {
#pragma unroll
    for (int it = 0; it < 8; ++it) {
        int lin = it * 128 + tid;            // 1024 float4 chunks
        int r = lin >> 4, c4 = (lin & 15) << 2;
        float4 v = *reinterpret_cast<const float4*>(src + r * rs + c4);
        float h0 = __bfloat162float(__float2bfloat16(v.x));
        float h1 = __bfloat162float(__float2bfloat16(v.y));
        float h2 = __bfloat162float(__float2bfloat16(v.z));
        float h3 = __bfloat162float(__float2bfloat16(v.w));
        uint2 H = make_uint2(pack2(v.x, v.y), pack2(v.z, v.w));
        uint2 L = make_uint2(pack2(v.x - h0, v.y - h1), pack2(v.z - h2, v.w - h3));
        *reinterpret_cast<uint2*>(Th + r * LDB + c4) = H;
        *reinterpret_cast<uint2*>(Tl + r * LDB + c4) = L;
    }
}
// stage one register row f[64] -> row r of hi/lo tiles
__device__ __forceinline__ void stageRow(__nv_bfloat16* Th, __nv_bfloat16* Tl,
                                         const float* f, int r) {
#pragma unroll
    for (int c = 0; c < 64; c += 4) {
        float h0 = __bfloat162float(__float2bfloat16(f[c]));
        float h1 = __bfloat162float(__float2bfloat16(f[c + 1]));
        float h2 = __bfloat162float(__float2bfloat16(f[c + 2]));
        float h3 = __bfloat162float(__float2bfloat16(f[c + 3]));
        *reinterpret_cast<uint2*>(Th + r * LDB + c) =
            make_uint2(pack2(f[c], f[c + 1]), pack2(f[c + 2], f[c + 3]));
        *reinterpret_cast<uint2*>(Tl + r * LDB + c) =
            make_uint2(pack2(f[c] - h0, f[c + 1] - h1),
                       pack2(f[c + 2] - h2, f[c + 3] - h3));
    }
}

// ---------------------------------------------------------------------------
// C[64x64 f32, stride LDC] = A x B (3-term bf16 split), 4 warps, 16 rows each.
// AROW: A fragment row_major (A stored (m,k)) else col_major (A stored (k,m)).
// BROW: B fragment row_major (B stored (k,n)) else col_major (B stored (n,k)).
// ---------------------------------------------------------------------------
template <bool AROW, bool BROW>
__device__ __forceinline__ void wgemm3(const __nv_bfloat16* Ah, const __nv_bfloat16* Al,
                                       const __nv_bfloat16* Bh, const __nv_bfloat16* Bl,
                                       float* C, int wid) {
    using LA = typename std::conditional<AROW, wmma::row_major, wmma::col_major>::type;
    using LB = typename std::conditional<BROW, wmma::row_major, wmma::col_major>::type;
    wmma::fragment<wmma::matrix_a, 16, 16, 16, __nv_bfloat16, LA> ah[4], al[4];
    int m0 = wid << 4;
#pragma unroll
    for (int kt = 0; kt < 4; ++kt) {
        int aoff = AROW ? m0 * LDB + (kt << 4) : m0 + (kt << 4) * LDB;
        wmma::load_matrix_sync(ah[kt], Ah + aoff, LDB);
        wmma::load_matrix_sync(al[kt], Al + aoff, LDB);
    }
#pragma unroll
    for (int nt = 0; nt < 4; ++nt) {
        wmma::fragment<wmma::accumulator, 16, 16, 16, float> c;
        wmma::fill_fragment(c, 0.0f);
#pragma unroll
        for (int kt = 0; kt < 4; ++kt) {
            int boff = BROW ? (kt << 4) * LDB + (nt << 4) : (kt << 4) + (nt << 4) * LDB;
            wmma::fragment<wmma::matrix_b, 16, 16, 16, __nv_bfloat16, LB> bh, bl;
            wmma::load_matrix_sync(bh, Bh + boff, LDB);
            wmma::load_matrix_sync(bl, Bl + boff, LDB);
            wmma::mma_sync(c, ah[kt], bh, c);
            wmma::mma_sync(c, ah[kt], bl, c);
            wmma::mma_sync(c, al[kt], bh, c);
        }
        wmma::store_matrix_sync(C + m0 * LDC + (nt << 4), c, LDC, wmma::mem_row_major);
    }
}

// ---------------------------------------------------------------------------
// qmean[bh][s][d] = mean_i Q[bh][i][s][d]
// ---------------------------------------------------------------------------
__global__ void qmean_kernel(const float* __restrict__ Q) {
    int bid = blockIdx.x;
    int bh = bid >> 4;
    int s = ((bid & 15) << 2) + (threadIdx.x >> 6);
    int d = threadIdx.x & 63;
    const float* base = Q + bh * 262144 + s * 64 + d;
    float acc = 0.f;
#pragma unroll 16
    for (int i = 0; i < 64; ++i) acc += base[i * 4096];
    g_qmean[(bh << 6 | s) * 64 + d] = acc * (1.0f / 64.0f);
}

// ---------------------------------------------------------------------------
// B: per (bh,j): S=scale*qbar_j K^T; R=softmax_t; ent; kbar=R K; (vbar=R V)
// grid 4096, 128 thr
// ---------------------------------------------------------------------------
__global__ void __launch_bounds__(128)
bstep_kernel(const float* __restrict__ Kg, const float* __restrict__ Vg,
             int use_qmean, int do_vbar) {
    int bid = blockIdx.x, bh = bid >> 6, j = bid & 63;
    extern __shared__ char sm[];
    __nv_bfloat16* Ah = reinterpret_cast<__nv_bfloat16*>(sm + OFF_AH);  // qbar -> R
    __nv_bfloat16* Al = reinterpret_cast<__nv_bfloat16*>(sm + OFF_AL);
    __nv_bfloat16* Kh = reinterpret_cast<__nv_bfloat16*>(sm + OFF_BH);
    __nv_bfloat16* Kl = reinterpret_cast<__nv_bfloat16*>(sm + OFF_BL);
    __nv_bfloat16* Vh = reinterpret_cast<__nv_bfloat16*>(sm + OFF_VH);
    __nv_bfloat16* Vl = reinterpret_cast<__nv_bfloat16*>(sm + OFF_VL);
    float* C = reinterpret_cast<float*>(sm + OFF_C);
    int tid = threadIdx.x, wid = tid >> 5;

    const float* Kb = Kg + bh * 262144 + j * 4096;
    const float* qb = use_qmean ? (g_qmean + (bh << 12))
                                : (g_qbar + bh * 262144 + j * 4096);
    stageHL(Ah, Al, qb, 64, tid);
    stageHL(Kh, Kl, Kb, 64, tid);
    if (do_vbar) stageHL(Vh, Vl, Vg + bh * 262144 + j * 4096, 64, tid);
    __syncthreads();

    // S[s][t] = qbar(s,d) . K(t,d):  A row_major, B col_major over K(t,d)
    wgemm3<true, false>(Ah, Al, Kh, Kl, C, wid);
    __syncthreads();

    if (tid < 64) {
        int s = tid;
        float f[64];
        float mx = -1e30f;
#pragma unroll
        for (int c = 0; c < 64; ++c) {
            f[c] = C[s * LDC + c] * SCALE;
            mx = fmaxf(mx, f[c]);
        }
        float sum = 0.f;
#pragma unroll
        for (int c = 0; c < 64; ++c) { f[c] = __expf(f[c] - mx); sum += f[c]; }
        float inv = 1.0f / sum, lsum = __logf(sum), e = 0.f;
#pragma unroll
        for (int c = 0; c < 64; ++c) {
            float rv = f[c] * inv;
            e += rv * (__logf(fmaxf(f[c], 1e-37f)) - lsum);
            f[c] = rv;
        }
        g_ent[((bh << 6) + s) * 64 + j] = -e;
        stageRow(Ah, Al, f, s);              // R replaces qbar
    }
    __syncthreads();

    // kbar[s][d] = R(s,t) K(t,d): both row_major
    wgemm3<true, true>(Ah, Al, Kh, Kl, C, wid);
    __syncthreads();
    if (tid < 64) {
        float* o = g_kbar + bh * 262144 + tid * 4096 + (j << 6);
#pragma unroll
        for (int c = 0; c < 64; c += 4) {
            const float* p = C + tid * LDC + c;
            *reinterpret_cast<float4*>(o + c) = make_float4(p[0], p[1], p[2], p[3]);
        }
    }
    if (do_vbar) {
        __syncthreads();
        wgemm3<true, true>(Ah, Al, Vh, Vl, C, wid);
        __syncthreads();
        if (tid < 64) {
            float* o = g_vbar + bh * 262144 + tid * 4096 + (j << 6);
#pragma unroll
            for (int c = 0; c < 64; c += 4) {
                const float* p = C + tid * LDC + c;
                *reinterpret_cast<float4*>(o + c) = make_float4(p[0], p[1], p[2], p[3]);
            }
        }
    }
}

// ---------------------------------------------------------------------------
// C (fused): per (bh,s): SL = scale*Q kbar^T + ent; L = softmax_j
//   non-final: qbar[j][d] = (sum_i L[i][j] Q[i][d]) / (sum_i L[i][j])
//   final:     out[i][d] = sum_j L[i][j] vbar[j][d]
// grid 4096, 128 thr
// ---------------------------------------------------------------------------
__global__ void __launch_bounds__(128)
cstep_kernel(const float* __restrict__ Qg, float* __restrict__ out, int is_final) {
    int bid = blockIdx.x, bh = bid >> 6, s = bid & 63;
    extern __shared__ char sm[];
    __nv_bfloat16* Qh = reinterpret_cast<__nv_bfloat16*>(sm + OFF_AH);
    __nv_bfloat16* Ql = reinterpret_cast<__nv_bfloat16*>(sm + OFF_AL);
    __nv_bfloat16* Bh = reinterpret_cast<__nv_bfloat16*>(sm + OFF_BH);  // kbar -> L
    __nv_bfloat16* Bl = reinterpret_cast<__nv_bfloat16*>(sm + OFF_BL);
    __nv_bfloat16* Vh = reinterpret_cast<__nv_bfloat16*>(sm + OFF_VH);
    __nv_bfloat16* Vl = reinterpret_cast<__nv_bfloat16*>(sm + OFF_VL);
    float* C = reinterpret_cast<float*>(sm + OFF_C);
    float* sEnt = reinterpret_cast<float*>(sm + OFF_W);
    float* sW = sEnt + 64;
    int tid = threadIdx.x, wid = tid >> 5;

    const float* Qb = Qg + bh * 262144 + s * 64;       // rows i, stride 4096
    stageHL(Qh, Ql, Qb, 4096, tid);
    stageHL(Bh, Bl, g_kbar + bh * 262144 + s * 4096, 64, tid);
    if (is_final) stageHL(Vh, Vl, g_vbar + bh * 262144 + s * 4096, 64, tid);
    if (tid < 64) sEnt[tid] = g_ent[((bh << 6) + s) * 64 + tid];
    __syncthreads();

    // SL[i][j] = Q(i,d) . kbar(j,d): A row_major, B col_major
    wgemm3<true, false>(Qh, Ql, Bh, Bl, C, wid);
    __syncthreads();

    if (tid < 64) {
        int i = tid;
        float f[64];
        float mx = -1e30f;
#pragma unroll
        for (int c = 0; c < 64; ++c) {
            f[c] = C[i * LDC + c] * SCALE + sEnt[c];
            mx = fmaxf(mx, f[c]);
        }
        float sum = 0.f;
#pragma unroll
        for (int c = 0; c < 64; ++c) { f[c] = __expf(f[c] - mx); sum += f[c]; }
        float inv = 1.0f / sum;
#pragma unroll
        for (int c = 0; c < 64; ++c) f[c] *= inv;      // L row i
        stageRow(Bh, Bl, f, i);                         // L replaces kbar
        if (!is_final) {
#pragma unroll
            for (int c = 0; c < 64; ++c) C[i * LDC + c] = f[c];  // fp32 L for w
        }
    }
    __syncthreads();

    if (!is_final) {
        if (tid < 64) {
            float w = 0.f;
#pragma unroll 8
            for (int i = 0; i < 64; ++i) w += C[i * LDC + tid];
            sW[tid] = 1.0f / w;
        }
        __syncthreads();
        // qbar_num[j][d] = sum_i L(i,j) Q(i,d): A col_major over L(i,j), B row_major
        wgemm3<false, true>(Bh, Bl, Qh, Ql, C, wid);
        __syncthreads();
        if (tid < 64) {
            float iw = sW[tid];
            float* o = g_qbar + bh * 262144 + tid * 4096 + (s << 6);
#pragma unroll
            for (int c = 0; c < 64; c += 4) {
                const float* p = C + tid * LDC + c;
                *reinterpret_cast<float4*>(o + c) =
                    make_float4(p[0] * iw, p[1] * iw, p[2] * iw, p[3] * iw);
            }
        }
    } else {
        // out[i][d] = sum_j L(i,j) vbar(j,d): both row_major
        wgemm3<true, true>(Bh, Bl, Vh, Vl, C, wid);
        __syncthreads();
        if (tid < 64) {
            float* o = out + bh * 262144 + tid * 4096 + (s << 6);
#pragma unroll
            for (int c = 0; c < 64; c += 4) {
                const float* p = C + tid * LDC + c;
                *reinterpret_cast<float4*>(o + c) = make_float4(p[0], p[1], p[2], p[3]);
            }
        }
    }
}

// ---------------------------------------------------------------------------
extern "C" void kernel_launch(void* const* d_in, const int* in_sizes, int n_in,
                              void* d_out, int out_size) {
    const float* Q = (const float*)d_in[0];
    const float* K = (const float*)d_in[1];
    const float* V = (const float*)d_in[2];
    float* out = (float*)d_out;

    cudaFuncSetAttribute(bstep_kernel, cudaFuncAttributeMaxDynamicSharedMemorySize, SMEM_BIG);
    cudaFuncSetAttribute(cstep_kernel, cudaFuncAttributeMaxDynamicSharedMemorySize, SMEM_BIG);

    // step 0 (uniform L -> qbar == per-s mean of Q)
    qmean_kernel<<<1024, 256>>>(Q);
    bstep_kernel<<<4096, 128, SMEM_SMALL>>>(K, V, 1, 0);
    cstep_kernel<<<4096, 128, SMEM_SMALL>>>(Q, out, 0);
    // step 1
    bstep_kernel<<<4096, 128, SMEM_SMALL>>>(K, V, 0, 0);
    cstep_kernel<<<4096, 128, SMEM_SMALL>>>(Q, out, 0);
    // step 2
    bstep_kernel<<<4096, 128, SMEM_BIG>>>(K, V, 0, 1);   // + vbar
    cstep_kernel<<<4096, 128, SMEM_BIG>>>(Q, out, 1);    // final: out = L vbar
}